// round 14
// baseline (speedup 1.0000x reference)
#include <cuda_runtime.h>
#include <math.h>

#define NP 512
#define NB 512
#define NAT 32
#define NBT 40
#define NC 3
#define NTAB 40
#define NG 36
#define NA (NB*NAT)
#define TPB 256
#define STPB 128
#define NCELL (NTAB*NG*NG)   // 51840 repacked table cells

// Repacked tables: for each (tab,row,c0), the 4 wrapped column taps as one float4.
__device__ float4 g_tbl4[NCELL];
// Per-item resolved gather indices (8 x u16) and meta (tab | ok<<8 | nb_ok<<9).
__device__ int4 g_pk[NP * NB];
__device__ int  g_meta[NP * NB];

__device__ __forceinline__ int wrapG(int v) {
    int m = v % NG;
    return (m < 0) ? m + NG : m;
}

__device__ __forceinline__ void cr_weights(float f, float w[4]) {
    float f2 = f * f;
    float f3 = f2 * f;
    w[0] = 0.5f * (-f3 + 2.0f * f2 - f);
    w[1] = 0.5f * (3.0f * f3 - 5.0f * f2 + 2.0f);
    w[2] = 0.5f * (-3.0f * f3 + 4.0f * f2 + f);
    w[3] = 0.5f * (f3 - f2);
}

__device__ __forceinline__ float dihedral(
    const float x[4], const float y[4], const float z[4])
{
    float b1x = x[1]-x[0], b1y = y[1]-y[0], b1z = z[1]-z[0];
    float b2x = x[2]-x[1], b2y = y[2]-y[1], b2z = z[2]-z[1];
    float b3x = x[3]-x[2], b3y = y[3]-y[2], b3z = z[3]-z[2];
    float n1x = b1y*b2z - b1z*b2y;
    float n1y = b1z*b2x - b1x*b2z;
    float n1z = b1x*b2y - b1y*b2x;
    float n2x = b2y*b3z - b2z*b3y;
    float n2y = b2z*b3x - b2x*b3z;
    float n2z = b2x*b3y - b2y*b3x;
    float b2n = sqrtf(b2x*b2x + b2y*b2y + b2z*b2z) + 1e-12f;
    float inv = 1.0f / b2n;
    float ux = b2x*inv, uy = b2y*inv, uz = b2z*inv;
    float m1x = n1y*uz - n1z*uy;
    float m1y = n1z*ux - n1x*uz;
    float m1z = n1x*uy - n1y*ux;
    float xx = n1x*n2x + n1y*n2y + n1z*n2z;
    float yy = m1x*n2x + m1y*n2y + m1z*n2z;
    return atan2f(yy, xx);
}

// Branchless xyz load: 1 unconditional LDG.128 + 1 LDG.64 predicated on r>=2.
__device__ __forceinline__ void load_xyz(
    const float4* __restrict__ cp4, const float2* __restrict__ cp2,
    int gidx, float& x, float& y, float& z)
{
    const int base = gidx * 3;
    const int r = base & 3;
    const float4 V = __ldg(cp4 + (base >> 2));
    float2 E = make_float2(0.0f, 0.0f);
    if (r >= 2) E = __ldg(cp2 + ((base + 2) >> 1));
    x = (r == 0) ? V.x : ((r == 1) ? V.y : ((r == 2) ? V.z : V.w));
    y = (r == 0) ? V.y : ((r == 1) ? V.z : ((r == 2) ? V.w : E.x));
    z = (r == 0) ? V.z : ((r == 1) ? V.w : ((r == 2) ? E.x : E.y));
}

// ===== Kernel A (fused): table repack slice + out zeroing + index resolution =====
__global__ __launch_bounds__(TPB, 4) void prep_kernel(
    const int*   __restrict__ offsets,       // (P, B)
    const int*   __restrict__ block_type,    // (P, B)
    const int*   __restrict__ inter,         // (P, B, NC, 2)
    const int*   __restrict__ down,          // (NBT, NC, NAT)
    const int*   __restrict__ bt_rama_table, // (NBT, 2)
    const int*   __restrict__ bt_upper,      // (NBT)
    const int*   __restrict__ bt_is_pro,     // (NBT)
    const int*   __restrict__ tor_atoms,     // (NBT, 8, 3)
    const float* __restrict__ tables,        // (NTAB, G, G)
    float*       __restrict__ out)           // (P,) -- zeroed here
{
    __shared__ int   s_offs[NB];
    __shared__ int   s_bt[NB];
    __shared__ int4  s_torpack[NBT];
    __shared__ alignas(16) int   s_down[NBT * NC * NAT];
    __shared__ int   s_tabsel[NBT * 2];
    __shared__ int   s_upper[NBT];
    __shared__ int   s_ispro[NBT];

    const int p   = blockIdx.x;
    const int tid = threadIdx.x;

    // ---- repack slice + out zeroing: flat index over the grid ----
    {
        const int idx = p * TPB + tid;          // 0 .. 131071
        if (idx < NP) out[idx] = 0.0f;
        if (idx < NCELL) {
            const int c0 = idx % NG;
            const float* row = tables + (idx / NG) * NG;
            int c1 = c0 + 1; if (c1 >= NG) c1 -= NG;
            int c2 = c0 + 2; if (c2 >= NG) c2 -= NG;
            int c3 = c0 + 3; if (c3 >= NG) c3 -= NG;
            g_tbl4[idx] = make_float4(row[c0], row[c1], row[c2], row[c3]);
        }
    }

    // ---- stage pose rows ----
    s_offs[tid]       = offsets[p * NB + tid];
    s_offs[tid + TPB] = offsets[p * NB + tid + TPB];
    s_bt[tid]         = block_type[p * NB + tid];
    s_bt[tid + TPB]   = block_type[p * NB + tid + TPB];
    {
        const int4* g4 = (const int4*)down;   // 960 int4
        int4* s4 = (int4*)s_down;
        #pragma unroll
        for (int i = tid; i < 960; i += TPB) s4[i] = g4[i];
    }
    if (tid < NBT) {
        const int* tr = tor_atoms + tid * 24;   // 8 slots x 3
        unsigned int w[4];
        #pragma unroll
        for (int h = 0; h < 4; h++) {
            unsigned int lo, hi;
            {
                const int s = 2 * h;
                const int ai = tr[s*3+0], ci = tr[s*3+1], nb = tr[s*3+2];
                lo = (unsigned int)(ai + 1) | ((unsigned int)(ci + 1) << 6)
                   | ((unsigned int)nb << 8);
            }
            {
                const int s = 2 * h + 1;
                const int ai = tr[s*3+0], ci = tr[s*3+1], nb = tr[s*3+2];
                hi = (unsigned int)(ai + 1) | ((unsigned int)(ci + 1) << 6)
                   | ((unsigned int)nb << 8);
            }
            w[h] = lo | (hi << 16);
        }
        s_torpack[tid] = make_int4((int)w[0], (int)w[1], (int)w[2], (int)w[3]);
    }
    if (tid < NBT * 2) s_tabsel[tid] = bt_rama_table[tid];
    if (tid < NBT)     { s_upper[tid] = bt_upper[tid]; s_ispro[tid] = bt_is_pro[tid]; }

    int iv[2][6];
    #pragma unroll
    for (int k = 0; k < 2; k++) {
        const int pb = p * NB + tid + k * TPB;
        const int2* ip2 = (const int2*)(inter + (size_t)pb * 6);
        const int2 a = __ldg(ip2 + 0), bb = __ldg(ip2 + 1), c = __ldg(ip2 + 2);
        iv[k][0] = a.x;  iv[k][1] = a.y;
        iv[k][2] = bb.x; iv[k][3] = bb.y;
        iv[k][4] = c.x;  iv[k][5] = c.y;
    }

    __syncthreads();

    #pragma unroll
    for (int k = 0; k < 2; k++) {
        const int b    = tid + k * TPB;
        const int pb   = p * NB + b;
        const int bt   = s_bt[b];
        const int offb = s_offs[b];
        const int4 tp4 = s_torpack[bt];
        bool okk = true;
        int g[8];
        #pragma unroll
        for (int t = 0; t < 8; t++) {
            const unsigned int word = (unsigned int)((t >> 1) == 0 ? tp4.x :
                                      (t >> 1) == 1 ? tp4.y :
                                      (t >> 1) == 2 ? tp4.z : tp4.w);
            const unsigned int field = (t & 1) ? (word >> 16) : (word & 0xffffu);
            const int ai     = (int)(field & 63u) - 1;
            const int ci     = (int)((field >> 6) & 3u) - 1;
            const int nbonds = (int)((field >> 8) & 31u);
            int gg;
            bool aok;
            if (ai >= 0) {
                gg = offb + ai;
                aok = true;
            } else {
                const int sc = max(ci, 0);
                const int ob = (sc == 0) ? iv[k][0] : ((sc == 1) ? iv[k][2] : iv[k][4]);
                const int oc = (sc == 0) ? iv[k][1] : ((sc == 1) ? iv[k][3] : iv[k][5]);
                aok = (ci >= 0) && (ob >= 0);
                const int obc = min(max(ob, 0), NB - 1);
                const int occ = min(max(oc, 0), NC - 1);
                const int obt = s_bt[obc];
                const int da  = s_down[(obt * NC + occ) * NAT + nbonds];
                gg = s_offs[obc] + da;
            }
            okk = okk && aok;
            g[t] = min(max(gg, 0), NA - 1);
        }

        const int uc    = min(max(s_upper[bt], 0), NC - 1);
        const int nbblk = (uc == 0) ? iv[k][0] : ((uc == 1) ? iv[k][2] : iv[k][4]);
        const bool nb_ok = (nbblk >= 0);
        const int nbt = s_bt[min(max(nbblk, 0), NB - 1)];
        const int tab = s_tabsel[bt * 2 + s_ispro[nbt]];

        int4 pk;
        pk.x = g[0] | (g[1] << 16);
        pk.y = g[2] | (g[3] << 16);
        pk.z = g[4] | (g[5] << 16);
        pk.w = g[6] | (g[7] << 16);
        g_pk[pb]   = pk;
        g_meta[pb] = tab | (okk ? 0x100 : 0) | (nb_ok ? 0x200 : 0);
    }
}

// ===== Kernel B (flat): 1 item/thread, 2048 blocks, warp-atomic reduce =====
__global__ __launch_bounds__(STPB, 10) void score_kernel(
    const float* __restrict__ coords,        // (P, NA, 3)
    const float* __restrict__ tparams,       // (NTAB, 2, 2)
    float*       __restrict__ out)           // (P,) pre-zeroed
{
    const int item = blockIdx.x * STPB + threadIdx.x;   // 0 .. NP*NB-1
    const int p    = item >> 9;                          // /NB

    const float4* cp4 = (const float4*)(coords + (size_t)p * NA * 3);
    const float2* cp2 = (const float2*)(coords + (size_t)p * NA * 3);

    const int4 pk  = __ldg(&g_pk[item]);
    const int meta = __ldg(&g_meta[item]);

    int gidx[8];
    gidx[0] = pk.x & 0xffff;  gidx[1] = ((unsigned)pk.x) >> 16;
    gidx[2] = pk.y & 0xffff;  gidx[3] = ((unsigned)pk.y) >> 16;
    gidx[4] = pk.z & 0xffff;  gidx[5] = ((unsigned)pk.z) >> 16;
    gidx[6] = pk.w & 0xffff;  gidx[7] = ((unsigned)pk.w) >> 16;

    float ax[8], ay[8], az[8];
    #pragma unroll
    for (int t = 0; t < 8; t++) {
        const bool dup = (t >= 4 && t <= 6) && (gidx[t] == gidx[t-3]);
        if (dup) {
            ax[t] = ax[t-3]; ay[t] = ay[t-3]; az[t] = az[t-3];
        } else {
            load_xyz(cp4, cp2, gidx[t], ax[t], ay[t], az[t]);
        }
    }

    const float phi = dihedral(&ax[0], &ay[0], &az[0]);
    const float psi = dihedral(&ax[4], &ay[4], &az[4]);

    const int tab = meta & 0xff;
    const float4 tp = __ldg((const float4*)tparams + tab);

    const float u0 = (phi - tp.x) / tp.z;
    const float u1 = (psi - tp.y) / tp.w;
    const float i0f = floorf(u0);
    const float j0f = floorf(u1);
    const float f0 = u0 - i0f;
    const float f1 = u1 - j0f;
    const int i0 = (int)i0f;
    const int j0 = (int)j0f;

    float wp[4], wq[4];
    cr_weights(f0, wp);
    cr_weights(f1, wq);

    const int c0 = wrapG(j0 - 1);
    const int tabbase = tab * NG * NG;

    float4 tv[4];
    #pragma unroll
    for (int i = 0; i < 4; i++) {
        const int ri = wrapG(i0 - 1 + i);
        tv[i] = __ldg(&g_tbl4[tabbase + ri * NG + c0]);
    }

    float e = 0.0f;
    #pragma unroll
    for (int i = 0; i < 4; i++) {
        float acc;
        acc = wq[0] * tv[i].x;
        acc = fmaf(wq[1], tv[i].y, acc);
        acc = fmaf(wq[2], tv[i].z, acc);
        acc = fmaf(wq[3], tv[i].w, acc);
        e = fmaf(wp[i], acc, e);
    }

    float v = (((meta >> 8) & 3) == 3) ? e : 0.0f;

    // warp reduce (all lanes of a warp share the same pose: 512 % 32 == 0)
    #pragma unroll
    for (int o = 16; o > 0; o >>= 1)
        v += __shfl_down_sync(0xffffffffu, v, o);
    if ((threadIdx.x & 31) == 0)
        atomicAdd(out + p, v);
}

extern "C" void kernel_launch(void* const* d_in, const int* in_sizes, int n_in,
                              void* d_out, int out_size) {
    const float* coords        = (const float*)d_in[0];
    const int*   offsets       = (const int*)d_in[1];
    const int*   block_type    = (const int*)d_in[2];
    const int*   inter         = (const int*)d_in[3];
    const int*   down          = (const int*)d_in[4];
    const int*   bt_rama_table = (const int*)d_in[5];
    const int*   bt_upper      = (const int*)d_in[6];
    const int*   bt_is_pro     = (const int*)d_in[7];
    const int*   tor_atoms     = (const int*)d_in[8];
    const float* tables        = (const float*)d_in[9];
    const float* tparams       = (const float*)d_in[10];
    float* out = (float*)d_out;

    prep_kernel<<<NP, TPB>>>(offsets, block_type, inter, down,
                             bt_rama_table, bt_upper, bt_is_pro, tor_atoms,
                             tables, out);
    score_kernel<<<(NP * NB) / STPB, STPB>>>(coords, tparams, out);
}

// round 15
// speedup vs baseline: 1.0769x; 1.0769x over previous
#include <cuda_runtime.h>
#include <math.h>

#define NP 512
#define NB 512
#define NAT 32
#define NBT 40
#define NC 3
#define NTAB 40
#define NG 36
#define NA (NB*NAT)
#define TPB 256
#define NCELL (NTAB*NG*NG)   // 51840 repacked table cells

// Repacked tables: for each (tab,row,c0), the 4 wrapped column taps as one float4.
__device__ float4 g_tbl4[NCELL];
// Per-item packed record: 4 words, each = idx_lo(14b) | idx_hi(14b)<<14 | nibble<<28.
// Nibbles of words x,y hold meta8 = tab(6b) | ok<<6 | nb_ok<<7.
__device__ int4 g_pk[NP * NB];

__device__ __forceinline__ int wrapG(int v) {
    int m = v % NG;
    return (m < 0) ? m + NG : m;
}

__device__ __forceinline__ void cr_weights(float f, float w[4]) {
    float f2 = f * f;
    float f3 = f2 * f;
    w[0] = 0.5f * (-f3 + 2.0f * f2 - f);
    w[1] = 0.5f * (3.0f * f3 - 5.0f * f2 + 2.0f);
    w[2] = 0.5f * (-3.0f * f3 + 4.0f * f2 + f);
    w[3] = 0.5f * (f3 - f2);
}

__device__ __forceinline__ float dihedral(
    const float x[4], const float y[4], const float z[4])
{
    float b1x = x[1]-x[0], b1y = y[1]-y[0], b1z = z[1]-z[0];
    float b2x = x[2]-x[1], b2y = y[2]-y[1], b2z = z[2]-z[1];
    float b3x = x[3]-x[2], b3y = y[3]-y[2], b3z = z[3]-z[2];
    float n1x = b1y*b2z - b1z*b2y;
    float n1y = b1z*b2x - b1x*b2z;
    float n1z = b1x*b2y - b1y*b2x;
    float n2x = b2y*b3z - b2z*b3y;
    float n2y = b2z*b3x - b2x*b3z;
    float n2z = b2x*b3y - b2y*b3x;
    float b2n = sqrtf(b2x*b2x + b2y*b2y + b2z*b2z) + 1e-12f;
    float inv = 1.0f / b2n;
    float ux = b2x*inv, uy = b2y*inv, uz = b2z*inv;
    float m1x = n1y*uz - n1z*uy;
    float m1y = n1z*ux - n1x*uz;
    float m1z = n1x*uy - n1y*ux;
    float xx = n1x*n2x + n1y*n2y + n1z*n2z;
    float yy = m1x*n2x + m1y*n2y + m1z*n2z;
    return atan2f(yy, xx);
}

// Branchless xyz load: 1 unconditional LDG.128 + 1 LDG.64 predicated on r>=2.
__device__ __forceinline__ void load_xyz(
    const float4* __restrict__ cp4, const float2* __restrict__ cp2,
    int gidx, float& x, float& y, float& z)
{
    const int base = gidx * 3;
    const int r = base & 3;
    const float4 V = __ldg(cp4 + (base >> 2));
    float2 E = make_float2(0.0f, 0.0f);
    if (r >= 2) E = __ldg(cp2 + ((base + 2) >> 1));
    x = (r == 0) ? V.x : ((r == 1) ? V.y : ((r == 2) ? V.z : V.w));
    y = (r == 0) ? V.y : ((r == 1) ? V.z : ((r == 2) ? V.w : E.x));
    z = (r == 0) ? V.z : ((r == 1) ? V.w : ((r == 2) ? E.x : E.y));
}

// ===== Kernel A (fused): table repack slice + index resolution =====
__global__ __launch_bounds__(TPB, 4) void prep_kernel(
    const int*   __restrict__ offsets,       // (P, B)
    const int*   __restrict__ block_type,    // (P, B)
    const int*   __restrict__ inter,         // (P, B, NC, 2)
    const int*   __restrict__ down,          // (NBT, NC, NAT)
    const int*   __restrict__ bt_rama_table, // (NBT, 2)
    const int*   __restrict__ bt_upper,      // (NBT)
    const int*   __restrict__ bt_is_pro,     // (NBT)
    const int*   __restrict__ tor_atoms,     // (NBT, 8, 3)
    const float* __restrict__ tables)        // (NTAB, G, G)
{
    __shared__ int   s_offs[NB];
    __shared__ int   s_bt[NB];
    __shared__ int4  s_torpack[NBT];
    __shared__ alignas(16) int   s_down[NBT * NC * NAT];
    __shared__ int   s_tabsel[NBT * 2];
    __shared__ int   s_upper[NBT];
    __shared__ int   s_ispro[NBT];

    const int p   = blockIdx.x;
    const int tid = threadIdx.x;

    // ---- repack slice: flat index over the grid (<=1 cell per thread) ----
    {
        const int idx = p * TPB + tid;          // 0 .. 131071
        if (idx < NCELL) {
            const int c0 = idx % NG;
            const float* row = tables + (idx / NG) * NG;
            int c1 = c0 + 1; if (c1 >= NG) c1 -= NG;
            int c2 = c0 + 2; if (c2 >= NG) c2 -= NG;
            int c3 = c0 + 3; if (c3 >= NG) c3 -= NG;
            g_tbl4[idx] = make_float4(row[c0], row[c1], row[c2], row[c3]);
        }
    }

    // ---- stage pose rows ----
    s_offs[tid]       = offsets[p * NB + tid];
    s_offs[tid + TPB] = offsets[p * NB + tid + TPB];
    s_bt[tid]         = block_type[p * NB + tid];
    s_bt[tid + TPB]   = block_type[p * NB + tid + TPB];
    {
        const int4* g4 = (const int4*)down;   // 960 int4
        int4* s4 = (int4*)s_down;
        #pragma unroll
        for (int i = tid; i < 960; i += TPB) s4[i] = g4[i];
    }
    if (tid < NBT) {
        const int* tr = tor_atoms + tid * 24;   // 8 slots x 3
        unsigned int w[4];
        #pragma unroll
        for (int h = 0; h < 4; h++) {
            unsigned int lo, hi;
            {
                const int s = 2 * h;
                const int ai = tr[s*3+0], ci = tr[s*3+1], nb = tr[s*3+2];
                lo = (unsigned int)(ai + 1) | ((unsigned int)(ci + 1) << 6)
                   | ((unsigned int)nb << 8);
            }
            {
                const int s = 2 * h + 1;
                const int ai = tr[s*3+0], ci = tr[s*3+1], nb = tr[s*3+2];
                hi = (unsigned int)(ai + 1) | ((unsigned int)(ci + 1) << 6)
                   | ((unsigned int)nb << 8);
            }
            w[h] = lo | (hi << 16);
        }
        s_torpack[tid] = make_int4((int)w[0], (int)w[1], (int)w[2], (int)w[3]);
    }
    if (tid < NBT * 2) s_tabsel[tid] = bt_rama_table[tid];
    if (tid < NBT)     { s_upper[tid] = bt_upper[tid]; s_ispro[tid] = bt_is_pro[tid]; }

    int iv[2][6];
    #pragma unroll
    for (int k = 0; k < 2; k++) {
        const int pb = p * NB + tid + k * TPB;
        const int2* ip2 = (const int2*)(inter + (size_t)pb * 6);
        const int2 a = __ldg(ip2 + 0), bb = __ldg(ip2 + 1), c = __ldg(ip2 + 2);
        iv[k][0] = a.x;  iv[k][1] = a.y;
        iv[k][2] = bb.x; iv[k][3] = bb.y;
        iv[k][4] = c.x;  iv[k][5] = c.y;
    }

    __syncthreads();

    #pragma unroll
    for (int k = 0; k < 2; k++) {
        const int b    = tid + k * TPB;
        const int pb   = p * NB + b;
        const int bt   = s_bt[b];
        const int offb = s_offs[b];
        const int4 tp4 = s_torpack[bt];
        bool okk = true;
        int g[8];
        #pragma unroll
        for (int t = 0; t < 8; t++) {
            const unsigned int word = (unsigned int)((t >> 1) == 0 ? tp4.x :
                                      (t >> 1) == 1 ? tp4.y :
                                      (t >> 1) == 2 ? tp4.z : tp4.w);
            const unsigned int field = (t & 1) ? (word >> 16) : (word & 0xffffu);
            const int ai     = (int)(field & 63u) - 1;
            const int ci     = (int)((field >> 6) & 3u) - 1;
            const int nbonds = (int)((field >> 8) & 31u);
            int gg;
            bool aok;
            if (ai >= 0) {
                gg = offb + ai;
                aok = true;
            } else {
                const int sc = max(ci, 0);
                const int ob = (sc == 0) ? iv[k][0] : ((sc == 1) ? iv[k][2] : iv[k][4]);
                const int oc = (sc == 0) ? iv[k][1] : ((sc == 1) ? iv[k][3] : iv[k][5]);
                aok = (ci >= 0) && (ob >= 0);
                const int obc = min(max(ob, 0), NB - 1);
                const int occ = min(max(oc, 0), NC - 1);
                const int obt = s_bt[obc];
                const int da  = s_down[(obt * NC + occ) * NAT + nbonds];
                gg = s_offs[obc] + da;
            }
            okk = okk && aok;
            g[t] = min(max(gg, 0), NA - 1);
        }

        const int uc    = min(max(s_upper[bt], 0), NC - 1);
        const int nbblk = (uc == 0) ? iv[k][0] : ((uc == 1) ? iv[k][2] : iv[k][4]);
        const bool nb_ok = (nbblk >= 0);
        const int nbt = s_bt[min(max(nbblk, 0), NB - 1)];
        const int tab = s_tabsel[bt * 2 + s_ispro[nbt]];

        // pack: word j = g[2j] | g[2j+1]<<14 | nibble<<28; nibbles of x,y = meta8
        const unsigned int meta8 = (unsigned int)tab
                                 | (okk ? 0x40u : 0u) | (nb_ok ? 0x80u : 0u);
        int4 pk;
        pk.x = (int)((unsigned)g[0] | ((unsigned)g[1] << 14) | ((meta8 & 0xFu) << 28));
        pk.y = (int)((unsigned)g[2] | ((unsigned)g[3] << 14) | ((meta8 >> 4) << 28));
        pk.z = (int)((unsigned)g[4] | ((unsigned)g[5] << 14));
        pk.w = (int)((unsigned)g[6] | ((unsigned)g[7] << 14));
        g_pk[pb] = pk;
    }
}

// ===== Kernel B: gather coords, dihedrals, table energy, reduce =====
__global__ __launch_bounds__(TPB, 4) void score_kernel(
    const float* __restrict__ coords,        // (P, NA, 3)
    const float* __restrict__ tparams,       // (NTAB, 2, 2)
    float*       __restrict__ out)           // (P,)
{
    __shared__ float s_warp[TPB / 32];

    const int p   = blockIdx.x;
    const int tid = threadIdx.x;

    const float4* cp4 = (const float4*)(coords + (size_t)p * NA * 3);
    const float2* cp2 = (const float2*)(coords + (size_t)p * NA * 3);

    int4 pk[2];
    #pragma unroll
    for (int k = 0; k < 2; k++)
        pk[k] = __ldg(&g_pk[p * NB + tid + k * TPB]);

    int gidx[2][8];
    unsigned int meta8[2];
    float ax[2][8], ay[2][8], az[2][8];
    #pragma unroll
    for (int k = 0; k < 2; k++) {
        const unsigned int wx = (unsigned)pk[k].x, wy = (unsigned)pk[k].y;
        const unsigned int wz = (unsigned)pk[k].z, ww = (unsigned)pk[k].w;
        gidx[k][0] = wx & 0x3FFF;  gidx[k][1] = (wx >> 14) & 0x3FFF;
        gidx[k][2] = wy & 0x3FFF;  gidx[k][3] = (wy >> 14) & 0x3FFF;
        gidx[k][4] = wz & 0x3FFF;  gidx[k][5] = (wz >> 14) & 0x3FFF;
        gidx[k][6] = ww & 0x3FFF;  gidx[k][7] = (ww >> 14) & 0x3FFF;
        meta8[k] = (wx >> 28) | ((wy >> 28) << 4);
        #pragma unroll
        for (int t = 0; t < 8; t++) {
            const bool dup = (t >= 4 && t <= 6) && (gidx[k][t] == gidx[k][t-3]);
            if (dup) {
                ax[k][t] = ax[k][t-3]; ay[k][t] = ay[k][t-3]; az[k][t] = az[k][t-3];
            } else {
                load_xyz(cp4, cp2, gidx[k][t], ax[k][t], ay[k][t], az[k][t]);
            }
        }
    }

    float v = 0.0f;
    #pragma unroll
    for (int k = 0; k < 2; k++) {
        const float phi = dihedral(&ax[k][0], &ay[k][0], &az[k][0]);
        const float psi = dihedral(&ax[k][4], &ay[k][4], &az[k][4]);

        const int tab = (int)(meta8[k] & 0x3Fu);
        const float4 tp = __ldg((const float4*)tparams + tab);

        const float u0 = __fdividef(phi - tp.x, tp.z);
        const float u1 = __fdividef(psi - tp.y, tp.w);
        const float i0f = floorf(u0);
        const float j0f = floorf(u1);
        const float f0 = u0 - i0f;
        const float f1 = u1 - j0f;
        const int i0 = (int)i0f;
        const int j0 = (int)j0f;

        float wp[4], wq[4];
        cr_weights(f0, wp);
        cr_weights(f1, wq);

        const int c0 = wrapG(j0 - 1);
        const int tabbase = tab * NG * NG;

        // incremental row wrap: one full wrap, then cheap increments
        int ri = wrapG(i0 - 1);
        float4 tv[4];
        #pragma unroll
        for (int i = 0; i < 4; i++) {
            tv[i] = __ldg(&g_tbl4[tabbase + ri * NG + c0]);
            ri = (ri + 1 < NG) ? ri + 1 : 0;
        }

        float e = 0.0f;
        #pragma unroll
        for (int i = 0; i < 4; i++) {
            float acc;
            acc = wq[0] * tv[i].x;
            acc = fmaf(wq[1], tv[i].y, acc);
            acc = fmaf(wq[2], tv[i].z, acc);
            acc = fmaf(wq[3], tv[i].w, acc);
            e = fmaf(wp[i], acc, e);
        }

        v += ((meta8[k] >> 6) == 3u) ? e : 0.0f;
    }

    const int lane = tid & 31;
    const int wid  = tid >> 5;
    #pragma unroll
    for (int o = 16; o > 0; o >>= 1)
        v += __shfl_down_sync(0xffffffffu, v, o);
    if (lane == 0) s_warp[wid] = v;
    __syncthreads();
    if (wid == 0) {
        float x = (lane < (TPB / 32)) ? s_warp[lane] : 0.0f;
        #pragma unroll
        for (int o = 4; o > 0; o >>= 1)
            x += __shfl_down_sync(0xffffffffu, x, o);
        if (lane == 0) out[p] = x;
    }
}

extern "C" void kernel_launch(void* const* d_in, const int* in_sizes, int n_in,
                              void* d_out, int out_size) {
    const float* coords        = (const float*)d_in[0];
    const int*   offsets       = (const int*)d_in[1];
    const int*   block_type    = (const int*)d_in[2];
    const int*   inter         = (const int*)d_in[3];
    const int*   down          = (const int*)d_in[4];
    const int*   bt_rama_table = (const int*)d_in[5];
    const int*   bt_upper      = (const int*)d_in[6];
    const int*   bt_is_pro     = (const int*)d_in[7];
    const int*   tor_atoms     = (const int*)d_in[8];
    const float* tables        = (const float*)d_in[9];
    const float* tparams       = (const float*)d_in[10];
    float* out = (float*)d_out;

    prep_kernel<<<NP, TPB>>>(offsets, block_type, inter, down,
                             bt_rama_table, bt_upper, bt_is_pro, tor_atoms,
                             tables);
    score_kernel<<<NP, TPB>>>(coords, tparams, out);
}